// round 10
// baseline (speedup 1.0000x reference)
#include <cuda_runtime.h>

#define N_ROWS 32768
#define F_IN   1024
#define F_OUT  512
#define FIX_CAP 8192
#define BANDR  2e-4               // relative band in e-space == abs band in s-space

// ---------------- device scratch (no allocations allowed) ----------------
__device__ float  g_w2hi[F_IN];        // W @ a2 hi part
__device__ float  g_w2lo[F_IN];        // W @ a2 lo part (double - hi)
__device__ double g_s0d;               // h . (W @ a1)        (atomic accum)
__device__ double g_sumpos;            // sum_j max(0, W@a2)  (atomic accum)
__device__ float  g_score32[N_ROWS];   // cheap fp32 scores
__device__ double g_Z;                 // sum_i exp(s_i - Cs) (atomic accum)
__device__ float  g_v[F_IN];           // sum_i e_i * adj[i]  (unnormalized)
__device__ float  g_invZ;
__device__ int    g_done;              // finished-block ticket
__device__ int    g_fixn;
__device__ int    g_fixrows[FIX_CAP];

// ---------------- helpers ----------------
__device__ __forceinline__ double warp_sum_d(double x) {
    #pragma unroll
    for (int off = 16; off > 0; off >>= 1)
        x += __shfl_down_sync(0xffffffffu, x, off);
    return x;
}
__device__ __forceinline__ float warp_sum_f(float x) {
    #pragma unroll
    for (int off = 16; off > 0; off >>= 1)
        x += __shfl_down_sync(0xffffffffu, x, off);
    return x;
}
__device__ __forceinline__ float2 ts_merge(float2 A, float2 B) {
    float s  = __fadd_rn(A.x, B.x);
    float bv = __fsub_rn(s, A.x);
    float av = __fsub_rn(s, bv);
    float e  = __fadd_rn(__fsub_rn(A.x, av), __fsub_rn(B.x, bv));
    return make_float2(s, __fadd_rn(__fadd_rn(A.y, B.y), e));
}
__device__ __forceinline__ float2 ts_addprod(float2 acc, float v, float whi, float wlo) {
    float p  = __fmul_rn(v, whi);
    float pe = __fmaf_rn(v, whi, -p);
    pe = __fmaf_rn(v, wlo, pe);
    return ts_merge(acc, make_float2(p, pe));
}
// Cs = leaky(C), C = s0 + sum_pos(w2): exact upper bound of scores (adj in [0,1))
__device__ __forceinline__ double shift_Cs() {
    double C = g_s0d + g_sumpos;
    return C > 0.0 ? C : ((double)0.1f) * C;
}

// ---------------- K_init ----------------
__global__ void k_init(float* out, int zero_out) {
    const int tid = threadIdx.x;           // 1024 threads, one block
    g_v[tid] = 0.0f;
    if (zero_out && tid < F_OUT) out[tid] = 0.0f;
    if (tid == 0) { g_s0d = 0.0; g_sumpos = 0.0; g_Z = 0.0; g_done = 0; g_fixn = 0; }
}

// ---------------- K1: w2 hi/lo, s0 (atomic), sumpos (atomic) ------------
__global__ void k_w12(const float* __restrict__ W, const float* __restrict__ a,
                      const float* __restrict__ h) {
    const int j   = blockIdx.x;            // 0..F_IN-1
    const int tid = threadIdx.x;           // 128 threads
    const float* __restrict__ row = W + (size_t)j * F_OUT;
    double p1 = 0.0, p2 = 0.0;
    for (int k = tid; k < F_OUT; k += 128) {
        double w = (double)row[k];
        p1 += w * (double)__ldg(a + k);
        p2 += w * (double)__ldg(a + F_OUT + k);
    }
    p1 = warp_sum_d(p1);
    p2 = warp_sum_d(p2);
    __shared__ double s1[4], s2[4];
    if ((tid & 31) == 0) { s1[tid >> 5] = p1; s2[tid >> 5] = p2; }
    __syncthreads();
    if (tid == 0) {
        double w1 = s1[0] + s1[1] + s1[2] + s1[3];
        double w2 = s2[0] + s2[1] + s2[2] + s2[3];
        float hi = (float)w2;
        g_w2hi[j] = hi;
        g_w2lo[j] = (float)(w2 - (double)hi);
        atomicAdd(&g_s0d, w1 * (double)h[j]);
        atomicAdd(&g_sumpos, w2 > 0.0 ? w2 : 0.0);
    }
}

// ---------------- K2 (fused): scores + e + v + Z + att2 epilogue --------
// 512 blocks x 256 thr = 8 warps; each warp handles 8 rows sequentially.
__global__ void __launch_bounds__(256) k_fused(const float* __restrict__ adj,
                                               float* __restrict__ att2,
                                               int write_att2) {
    __shared__ float4 sh_w[256];           // w2hi
    __shared__ float  sh_v[F_IN];
    __shared__ double sh_z[8];
    __shared__ int    sh_last;
    const int tid  = threadIdx.x;
    const int wid  = tid >> 5;
    const int lane = tid & 31;

    sh_w[tid] = reinterpret_cast<const float4*>(g_w2hi)[tid];
    sh_v[tid]       = 0.0f;
    sh_v[tid + 256] = 0.0f;
    sh_v[tid + 512] = 0.0f;
    sh_v[tid + 768] = 0.0f;
    __syncthreads();

    const double s0 = g_s0d;
    const double Cs = shift_Cs();
    const float  Csf_s0 = 0.0f;  (void)Csf_s0;

    float4 vacc[8];
    #pragma unroll
    for (int u = 0; u < 8; u++) vacc[u] = make_float4(0.f, 0.f, 0.f, 0.f);
    double zsum = 0.0;

    const int row0 = blockIdx.x * 64 + wid * 8;
    #pragma unroll 1
    for (int r = 0; r < 8; r++) {
        const int row = row0 + r;
        const float4* __restrict__ vp =
            reinterpret_cast<const float4*>(adj + (size_t)row * F_IN);
        float4 v[8];
        #pragma unroll
        for (int u = 0; u < 8; u++) v[u] = vp[u * 32 + lane];

        float dx = 0.f, dy = 0.f, dz = 0.f, dw = 0.f;
        #pragma unroll
        for (int u = 0; u < 8; u++) {
            const float4 wh = sh_w[u * 32 + lane];
            dx = __fmaf_rn(v[u].x, wh.x, dx);
            dy = __fmaf_rn(v[u].y, wh.y, dy);
            dz = __fmaf_rn(v[u].z, wh.z, dz);
            dw = __fmaf_rn(v[u].w, wh.w, dw);
        }
        float d = warp_sum_f(__fadd_rn(__fadd_rn(dx, dy), __fadd_rn(dz, dw)));

        float e;
        if (lane == 0) {
            double sc = (double)d + s0;
            sc = sc > 0.0 ? sc : ((double)0.1f) * sc;   // jax fp32 alpha
            g_score32[row] = (float)sc;
            e = expf((float)(sc - Cs));
            zsum += (double)e;
        }
        e = __shfl_sync(0xffffffffu, e, 0);

        #pragma unroll
        for (int u = 0; u < 8; u++) {
            vacc[u].x = __fmaf_rn(e, v[u].x, vacc[u].x);
            vacc[u].y = __fmaf_rn(e, v[u].y, vacc[u].y);
            vacc[u].z = __fmaf_rn(e, v[u].z, vacc[u].z);
            vacc[u].w = __fmaf_rn(e, v[u].w, vacc[u].w);
        }
    }

    if (lane == 0) sh_z[wid] = zsum;

    #pragma unroll
    for (int u = 0; u < 8; u++) {
        const int base = (u * 32 + lane) * 4;
        atomicAdd(&sh_v[base + 0], vacc[u].x);
        atomicAdd(&sh_v[base + 1], vacc[u].y);
        atomicAdd(&sh_v[base + 2], vacc[u].z);
        atomicAdd(&sh_v[base + 3], vacc[u].w);
    }
    __syncthreads();

    if (tid == 0) {
        double z = 0.0;
        #pragma unroll
        for (int w = 0; w < 8; w++) z += sh_z[w];
        atomicAdd(&g_Z, z);
    }
    const float4 sv = reinterpret_cast<const float4*>(sh_v)[tid];
    atomicAdd(&g_v[tid * 4 + 0], sv.x);
    atomicAdd(&g_v[tid * 4 + 1], sv.y);
    atomicAdd(&g_v[tid * 4 + 2], sv.z);
    atomicAdd(&g_v[tid * 4 + 3], sv.w);

    // ---- last-block epilogue: invZ + attention2 + band flags ----
    __threadfence();
    __syncthreads();
    if (tid == 0) {
        int t = atomicAdd(&g_done, 1);
        sh_last = (t == (int)gridDim.x - 1) ? 1 : 0;
    }
    __syncthreads();
    if (!sh_last) return;

    __shared__ double sh_eN;
    if (tid == 0) {
        double Zd = atomicAdd(&g_Z, 0.0);   // coherent read
        g_invZ = (float)(1.0 / Zd);
        sh_eN = Zd * (1.0 / (double)N_ROWS);
    }
    __syncthreads();
    if (!write_att2) return;
    const double eN   = sh_eN;
    const double band = BANDR * eN;
    const float  Csf  = 0.0f; (void)Csf;
    for (int i = tid; i < N_ROWS; i += 256) {
        double e = (double)expf((float)((double)g_score32[i] - Cs));
        att2[i] = (e > eN) ? 1.0f : 0.0f;
        if (fabs(e - eN) < band) {
            int k = atomicAdd(&g_fixn, 1);
            if (k < FIX_CAP) g_fixrows[k] = i;
        }
    }
}

// ---------------- K3: precise recompute of flagged rows (warp per row) --
__global__ void k_fixup(const float* __restrict__ adj, float* __restrict__ att2) {
    const double s0 = g_s0d;
    const double Cs = shift_Cs();
    const double eN = (double)(1.0) / ((double)N_ROWS * (double)g_invZ); // Z/N
    const int lane = threadIdx.x & 31;
    const int gw   = (blockIdx.x * blockDim.x + threadIdx.x) >> 5;
    const int nw   = (gridDim.x * blockDim.x) >> 5;
    int n = g_fixn; if (n > FIX_CAP) n = FIX_CAP;

    for (int k = gw; k < n; k += nw) {
        const int row = g_fixrows[k];
        const float4* __restrict__ vp =
            reinterpret_cast<const float4*>(adj + (size_t)row * F_IN);
        float2 acc = make_float2(0.f, 0.f);
        #pragma unroll
        for (int u = 0; u < 8; u++) {
            const float4 v  = vp[u * 32 + lane];
            const float4 wh = reinterpret_cast<const float4*>(g_w2hi)[u * 32 + lane];
            const float4 wl = reinterpret_cast<const float4*>(g_w2lo)[u * 32 + lane];
            acc = ts_addprod(acc, v.x, wh.x, wl.x);
            acc = ts_addprod(acc, v.y, wh.y, wl.y);
            acc = ts_addprod(acc, v.z, wh.z, wl.z);
            acc = ts_addprod(acc, v.w, wh.w, wl.w);
        }
        double d = (double)acc.x + (double)acc.y;
        #pragma unroll
        for (int off = 16; off > 0; off >>= 1)
            d += __shfl_down_sync(0xffffffffu, d, off);
        if (lane == 0) {
            double sc = d + s0;
            sc = sc > 0.0 ? sc : ((double)0.1f) * sc;
            att2[row] = (exp(sc - Cs) > eN) ? 1.0f : 0.0f;  // double exp, no log
        }
    }
}

// ---------------- K4: out[k] = invZ * sum_j v[j] * W1[j,k] --------------
__global__ void k_out(const float* __restrict__ W1, float* __restrict__ out) {
    const int k  = threadIdx.x;            // 0..511
    const int j0 = blockIdx.x * 16;
    float acc = 0.f;
    #pragma unroll
    for (int j = 0; j < 16; j++)
        acc = __fmaf_rn(g_v[j0 + j], W1[(size_t)(j0 + j) * F_OUT + k], acc);
    atomicAdd(&out[k], acc * g_invZ);
}

// ---------------- launch ----------------
extern "C" void kernel_launch(void* const* d_in, const int* in_sizes, int n_in,
                              void* d_out, int out_size) {
    const float* h   = (const float*)d_in[0];
    const float* adj = (const float*)d_in[1];
    const float* W   = (const float*)d_in[2];
    const float* a   = (const float*)d_in[3];
    const float* W1  = (const float*)d_in[4];
    float* out = (float*)d_out;

    // Output layout (confirmed passing in R5..R8):
    //   >= 33280 : [out(512) | attention2(32768)]
    //   == 512   : out only
    //   == 32768 : attention2 only
    bool  want_out = true;
    float* att2    = nullptr;
    if (out_size >= F_OUT + N_ROWS) {
        att2 = out + F_OUT;
    } else if (out_size == N_ROWS) {
        att2 = out;
        want_out = false;
    }

    k_init<<<1, 1024>>>(out, want_out ? 1 : 0);
    k_w12<<<F_IN, 128>>>(W, a, h);
    k_fused<<<N_ROWS / 64, 256>>>(adj, att2 ? att2 : (float*)d_out, att2 != nullptr ? 1 : 0);
    if (att2) k_fixup<<<32, 256>>>(adj, att2);
    if (want_out) k_out<<<F_IN / 16, F_OUT>>>(W1, out);
}

// round 12
// speedup vs baseline: 2.0997x; 2.0997x over previous
#include <cuda_runtime.h>

#define N_ROWS 32768
#define F_IN   1024
#define F_OUT  512
#define BANDR  2e-4f

// ---------------- device scratch (no allocations allowed) ----------------
// Packed so ONE cudaMemsetAsync graph node zeroes all per-call accumulators.
struct Acc {
    float  v[F_IN];        // sum_i e_i * adj[i]
    double s0;             // h . (W @ a1)
    double sumpos;         // sum_j max(0, W@a2)
    double Z;              // sum_i exp(s_i - Cs)
};
__device__ Acc   g_acc;
__device__ float g_w2hi[F_IN];
__device__ float g_w2lo[F_IN];
__device__ float g_score32[N_ROWS];

// ---------------- helpers ----------------
__device__ __forceinline__ double warp_sum_d(double x) {
    #pragma unroll
    for (int off = 16; off > 0; off >>= 1)
        x += __shfl_down_sync(0xffffffffu, x, off);
    return x;
}
__device__ __forceinline__ float warp_sum_f(float x) {
    #pragma unroll
    for (int off = 16; off > 0; off >>= 1)
        x += __shfl_down_sync(0xffffffffu, x, off);
    return x;
}
__device__ __forceinline__ float2 ts_merge(float2 A, float2 B) {
    float s  = __fadd_rn(A.x, B.x);
    float bv = __fsub_rn(s, A.x);
    float av = __fsub_rn(s, bv);
    float e  = __fadd_rn(__fsub_rn(A.x, av), __fsub_rn(B.x, bv));
    return make_float2(s, __fadd_rn(__fadd_rn(A.y, B.y), e));
}
__device__ __forceinline__ float2 ts_addprod(float2 acc, float v, float whi, float wlo) {
    float p  = __fmul_rn(v, whi);
    float pe = __fmaf_rn(v, whi, -p);
    pe = __fmaf_rn(v, wlo, pe);
    return ts_merge(acc, make_float2(p, pe));
}
// Cs = leaky(C), C = s0 + sum_pos(w2): exact upper bound of scores (adj in [0,1))
__device__ __forceinline__ double shift_Cs(double s0, double sumpos) {
    double C = s0 + sumpos;
    return C > 0.0 ? C : ((double)0.1f) * C;
}

// ---------------- K1: w2 hi/lo, s0 (atomic), sumpos (atomic) ------------
__global__ void k_w12(const float* __restrict__ W, const float* __restrict__ a,
                      const float* __restrict__ h) {
    const int j   = blockIdx.x;            // 0..F_IN-1
    const int tid = threadIdx.x;           // 128 threads
    const float* __restrict__ row = W + (size_t)j * F_OUT;
    double p1 = 0.0, p2 = 0.0;
    for (int k = tid; k < F_OUT; k += 128) {
        double w = (double)row[k];
        p1 += w * (double)__ldg(a + k);
        p2 += w * (double)__ldg(a + F_OUT + k);
    }
    p1 = warp_sum_d(p1);
    p2 = warp_sum_d(p2);
    __shared__ double s1[4], s2[4];
    if ((tid & 31) == 0) { s1[tid >> 5] = p1; s2[tid >> 5] = p2; }
    __syncthreads();
    if (tid == 0) {
        double w1 = s1[0] + s1[1] + s1[2] + s1[3];
        double w2 = s2[0] + s2[1] + s2[2] + s2[3];
        float hi = (float)w2;
        g_w2hi[j] = hi;
        g_w2lo[j] = (float)(w2 - (double)hi);
        atomicAdd(&g_acc.s0, w1 * (double)h[j]);
        atomicAdd(&g_acc.sumpos, w2 > 0.0 ? w2 : 0.0);
    }
}

// ---------------- K2 (fused): scores + e + v + Z, ONE adj pass ----------
// R6-proven shape: 512 blocks x 256 thr (8 warps); warp handles 8 rows.
__global__ void __launch_bounds__(256) k_fused(const float* __restrict__ adj) {
    __shared__ float4 sh_w[256];           // w2hi
    __shared__ float  sh_v[F_IN];
    __shared__ double sh_z[8];
    const int tid  = threadIdx.x;
    const int wid  = tid >> 5;
    const int lane = tid & 31;

    sh_w[tid] = reinterpret_cast<const float4*>(g_w2hi)[tid];
    sh_v[tid]       = 0.0f;
    sh_v[tid + 256] = 0.0f;
    sh_v[tid + 512] = 0.0f;
    sh_v[tid + 768] = 0.0f;
    __syncthreads();

    const double s0 = g_acc.s0;
    const double Cs = shift_Cs(s0, g_acc.sumpos);

    float4 vacc[8];
    #pragma unroll
    for (int u = 0; u < 8; u++) vacc[u] = make_float4(0.f, 0.f, 0.f, 0.f);
    double zsum = 0.0;

    const int row0 = blockIdx.x * 64 + wid * 8;
    for (int r = 0; r < 8; r++) {
        const int row = row0 + r;
        const float4* __restrict__ vp =
            reinterpret_cast<const float4*>(adj + (size_t)row * F_IN);
        float4 v[8];
        #pragma unroll
        for (int u = 0; u < 8; u++) v[u] = vp[u * 32 + lane];

        // plain fp32 dot, 4 independent fmaf chains
        float dx = 0.f, dy = 0.f, dz = 0.f, dw = 0.f;
        #pragma unroll
        for (int u = 0; u < 8; u++) {
            const float4 wh = sh_w[u * 32 + lane];
            dx = __fmaf_rn(v[u].x, wh.x, dx);
            dy = __fmaf_rn(v[u].y, wh.y, dy);
            dz = __fmaf_rn(v[u].z, wh.z, dz);
            dw = __fmaf_rn(v[u].w, wh.w, dw);
        }
        float d = warp_sum_f(__fadd_rn(__fadd_rn(dx, dy), __fadd_rn(dz, dw)));

        float e;
        if (lane == 0) {
            double sc = (double)d + s0;
            sc = sc > 0.0 ? sc : ((double)0.1f) * sc;   // jax fp32 alpha
            g_score32[row] = (float)sc;
            e = expf((float)(sc - Cs));
            zsum += (double)e;
        }
        e = __shfl_sync(0xffffffffu, e, 0);

        #pragma unroll
        for (int u = 0; u < 8; u++) {
            vacc[u].x = __fmaf_rn(e, v[u].x, vacc[u].x);
            vacc[u].y = __fmaf_rn(e, v[u].y, vacc[u].y);
            vacc[u].z = __fmaf_rn(e, v[u].z, vacc[u].z);
            vacc[u].w = __fmaf_rn(e, v[u].w, vacc[u].w);
        }
    }

    if (lane == 0) sh_z[wid] = zsum;

    #pragma unroll
    for (int u = 0; u < 8; u++) {
        const int base = (u * 32 + lane) * 4;
        atomicAdd(&sh_v[base + 0], vacc[u].x);
        atomicAdd(&sh_v[base + 1], vacc[u].y);
        atomicAdd(&sh_v[base + 2], vacc[u].z);
        atomicAdd(&sh_v[base + 3], vacc[u].w);
    }
    __syncthreads();

    if (tid == 0) {
        double z = 0.0;
        #pragma unroll
        for (int w = 0; w < 8; w++) z += sh_z[w];
        atomicAdd(&g_acc.Z, z);
    }
    const float4 sv = reinterpret_cast<const float4*>(sh_v)[tid];
    atomicAdd(&g_acc.v[tid * 4 + 0], sv.x);
    atomicAdd(&g_acc.v[tid * 4 + 1], sv.y);
    atomicAdd(&g_acc.v[tid * 4 + 2], sv.z);
    atomicAdd(&g_acc.v[tid * 4 + 3], sv.w);
}

// ---------------- K3 (merged): att2 + inline fixup | out GEMV ----------
// grid = 128 blocks x 512 thr.
//   blocks 0..63  : attention2 for 512 rows each (+ band fixup in-block)
//   blocks 64..127: out[k] partial over 16 j-values each
__global__ void __launch_bounds__(512) k_post(const float* __restrict__ adj,
                                              const float* __restrict__ W1,
                                              float* __restrict__ att2,
                                              float* __restrict__ out,
                                              int write_att2, int want_out) {
    const int b   = blockIdx.x;
    const int tid = threadIdx.x;

    if (b < 64) {
        if (!write_att2) return;
        __shared__ int sh_n;
        __shared__ int sh_rows[64];
        if (tid == 0) sh_n = 0;
        __syncthreads();

        const double s0 = g_acc.s0;
        const double Cs = shift_Cs(s0, g_acc.sumpos);
        const double eN = g_acc.Z * (1.0 / (double)N_ROWS);   // att>1/N <=> e>Z/N
        const float  eNf   = (float)eN;
        const float  bandf = BANDR * eNf;

        const int row = b * 512 + tid;
        const float s = g_score32[row];
        const float e = expf((float)((double)s - Cs));
        att2[row] = (e > eNf) ? 1.0f : 0.0f;
        if (fabsf(e - eNf) < bandf) {
            int k = atomicAdd(&sh_n, 1);
            if (k < 64) sh_rows[k] = row;
        }
        __syncthreads();

        int n = sh_n; if (n > 64) n = 64;
        const int wid  = tid >> 5;
        const int lane = tid & 31;
        for (int k = wid; k < n; k += 16) {           // warp per flagged row
            const int r = sh_rows[k];
            const float4* __restrict__ vp =
                reinterpret_cast<const float4*>(adj + (size_t)r * F_IN);
            float2 acc = make_float2(0.f, 0.f);
            #pragma unroll
            for (int u = 0; u < 8; u++) {
                const float4 v  = vp[u * 32 + lane];
                const float4 wh = reinterpret_cast<const float4*>(g_w2hi)[u * 32 + lane];
                const float4 wl = reinterpret_cast<const float4*>(g_w2lo)[u * 32 + lane];
                acc = ts_addprod(acc, v.x, wh.x, wl.x);
                acc = ts_addprod(acc, v.y, wh.y, wl.y);
                acc = ts_addprod(acc, v.z, wh.z, wl.z);
                acc = ts_addprod(acc, v.w, wh.w, wl.w);
            }
            double d = (double)acc.x + (double)acc.y;
            #pragma unroll
            for (int off = 16; off > 0; off >>= 1)
                d += __shfl_down_sync(0xffffffffu, d, off);
            if (lane == 0) {
                double sc = d + s0;
                sc = sc > 0.0 ? sc : ((double)0.1f) * sc;
                att2[r] = (exp(sc - Cs) > eN) ? 1.0f : 0.0f;   // double, no log
            }
        }
    } else {
        if (!want_out) return;
        __shared__ float sh_invZ;
        if (tid == 0) sh_invZ = (float)(1.0 / g_acc.Z);
        __syncthreads();
        const int k  = tid;                 // 0..511
        const int j0 = (b - 64) * 16;
        float acc = 0.f;
        #pragma unroll
        for (int j = 0; j < 16; j++)
            acc = __fmaf_rn(g_acc.v[j0 + j], W1[(size_t)(j0 + j) * F_OUT + k], acc);
        atomicAdd(&out[k], acc * sh_invZ);  // out zeroed by memset node
    }
}

// ---------------- launch ----------------
extern "C" void kernel_launch(void* const* d_in, const int* in_sizes, int n_in,
                              void* d_out, int out_size) {
    const float* h   = (const float*)d_in[0];
    const float* adj = (const float*)d_in[1];
    const float* W   = (const float*)d_in[2];
    const float* a   = (const float*)d_in[3];
    const float* W1  = (const float*)d_in[4];
    float* out = (float*)d_out;

    // Output layout (confirmed passing R5..R10):
    //   >= 33280 : [out(512) | attention2(32768)]
    //   == 512   : out only
    //   == 32768 : attention2 only
    bool  want_out = true;
    float* att2    = nullptr;
    if (out_size >= F_OUT + N_ROWS) {
        att2 = out + F_OUT;
    } else if (out_size == N_ROWS) {
        att2 = out;
        want_out = false;
    }

    // Zero accumulators via memset nodes (replaces k_init kernel).
    void* acc_ptr = nullptr;
    cudaGetSymbolAddress(&acc_ptr, g_acc);
    cudaMemsetAsync(acc_ptr, 0, sizeof(Acc), 0);
    if (want_out) cudaMemsetAsync(out, 0, F_OUT * sizeof(float), 0);

    k_w12<<<F_IN, 128>>>(W, a, h);
    k_fused<<<N_ROWS / 64, 256>>>(adj);
    k_post<<<128, 512>>>(adj, W1,
                         att2 ? att2 : out, out,
                         att2 != nullptr ? 1 : 0, want_out ? 1 : 0);
}

// round 14
// speedup vs baseline: 2.2154x; 1.0551x over previous
#include <cuda_runtime.h>

#define N_ROWS 32768
#define F_IN   1024
#define F_OUT  512
#define BANDR  2e-4f

// ---------------- device scratch (no allocations allowed) ----------------
// Packed so ONE cudaMemsetAsync graph node zeroes all per-call accumulators.
struct Acc {
    float  v[F_IN];        // sum_i e_i * adj[i]
    double s0;             // h . (W @ a1)
    double sumpos;         // sum_j max(0, W@a2)
    double Z;              // sum_i exp(s_i - Cs)
};
__device__ Acc   g_acc;
__device__ float g_w2hi[F_IN];
__device__ float g_w2lo[F_IN];
__device__ float g_score32[N_ROWS];

// ---------------- helpers ----------------
__device__ __forceinline__ float warp_sum_f(float x) {
    #pragma unroll
    for (int off = 16; off > 0; off >>= 1)
        x += __shfl_down_sync(0xffffffffu, x, off);
    return x;
}
__device__ __forceinline__ float2 ts_merge(float2 A, float2 B) {
    float s  = __fadd_rn(A.x, B.x);
    float bv = __fsub_rn(s, A.x);
    float av = __fsub_rn(s, bv);
    float e  = __fadd_rn(__fsub_rn(A.x, av), __fsub_rn(B.x, bv));
    return make_float2(s, __fadd_rn(__fadd_rn(A.y, B.y), e));
}
__device__ __forceinline__ float2 ts_addprod(float2 acc, float v, float whi, float wlo) {
    float p  = __fmul_rn(v, whi);
    float pe = __fmaf_rn(v, whi, -p);
    pe = __fmaf_rn(v, wlo, pe);
    return ts_merge(acc, make_float2(p, pe));
}
// single-product version (wlo = 0)
__device__ __forceinline__ float2 ts_addprod1(float2 acc, float v, float w) {
    float p  = __fmul_rn(v, w);
    float pe = __fmaf_rn(v, w, -p);
    return ts_merge(acc, make_float2(p, pe));
}
__device__ __forceinline__ float2 warp_ts_reduce(float2 acc) {
    #pragma unroll
    for (int off = 16; off > 0; off >>= 1) {
        float2 o;
        o.x = __shfl_down_sync(0xffffffffu, acc.x, off);
        o.y = __shfl_down_sync(0xffffffffu, acc.y, off);
        acc = ts_merge(acc, o);
    }
    return acc;
}
// Cs = leaky(C), C = s0 + sum_pos(w2): exact upper bound of scores (adj in [0,1))
__device__ __forceinline__ double shift_Cs(double s0, double sumpos) {
    double C = s0 + sumpos;
    return C > 0.0 ? C : ((double)0.1f) * C;
}

// ---------------- K1: w2 hi/lo, s0 (atomic), sumpos (atomic) ------------
// 128 blocks x 256 thr (8 warps); warp-per-row, compensated fp32 dots.
__global__ void __launch_bounds__(256) k_w12(const float* __restrict__ W,
                                             const float* __restrict__ a,
                                             const float* __restrict__ h) {
    const int wid  = threadIdx.x >> 5;
    const int lane = threadIdx.x & 31;
    const int j    = blockIdx.x * 8 + wid;             // 0..F_IN-1
    const float4* __restrict__ rw = reinterpret_cast<const float4*>(W + (size_t)j * F_OUT);
    const float4* __restrict__ a1 = reinterpret_cast<const float4*>(a);
    const float4* __restrict__ a2 = reinterpret_cast<const float4*>(a + F_OUT);

    float2 acc1 = make_float2(0.f, 0.f);
    float2 acc2 = make_float2(0.f, 0.f);
    #pragma unroll
    for (int u = 0; u < 4; u++) {
        const float4 w4 = rw[u * 32 + lane];
        const float4 b1 = __ldg(a1 + u * 32 + lane);
        const float4 b2 = __ldg(a2 + u * 32 + lane);
        acc1 = ts_addprod1(acc1, w4.x, b1.x);
        acc1 = ts_addprod1(acc1, w4.y, b1.y);
        acc1 = ts_addprod1(acc1, w4.z, b1.z);
        acc1 = ts_addprod1(acc1, w4.w, b1.w);
        acc2 = ts_addprod1(acc2, w4.x, b2.x);
        acc2 = ts_addprod1(acc2, w4.y, b2.y);
        acc2 = ts_addprod1(acc2, w4.z, b2.z);
        acc2 = ts_addprod1(acc2, w4.w, b2.w);
    }
    acc1 = warp_ts_reduce(acc1);
    acc2 = warp_ts_reduce(acc2);
    if (lane == 0) {
        double w1 = (double)acc1.x + (double)acc1.y;
        double w2 = (double)acc2.x + (double)acc2.y;
        float hi = (float)w2;
        g_w2hi[j] = hi;
        g_w2lo[j] = (float)(w2 - (double)hi);
        atomicAdd(&g_acc.s0, w1 * (double)h[j]);
        atomicAdd(&g_acc.sumpos, w2 > 0.0 ? w2 : 0.0);
    }
}

// ---------------- K2 (fused): scores + e + v + Z, ONE adj pass ----------
// 512 blocks x 256 thr (8 warps); warp handles 8 rows; w2hi in REGISTERS.
__global__ void __launch_bounds__(256) k_fused(const float* __restrict__ adj) {
    __shared__ float  sh_v[F_IN];
    __shared__ double sh_z[8];
    const int tid  = threadIdx.x;
    const int wid  = tid >> 5;
    const int lane = tid & 31;

    sh_v[tid]       = 0.0f;
    sh_v[tid + 256] = 0.0f;
    sh_v[tid + 512] = 0.0f;
    sh_v[tid + 768] = 0.0f;

    // w2hi lane-slice resident in registers for the whole kernel
    float4 wreg[8];
    #pragma unroll
    for (int u = 0; u < 8; u++)
        wreg[u] = reinterpret_cast<const float4*>(g_w2hi)[u * 32 + lane];

    __syncthreads();

    const double s0 = g_acc.s0;
    const double Cs = shift_Cs(s0, g_acc.sumpos);

    float4 vacc[8];
    #pragma unroll
    for (int u = 0; u < 8; u++) vacc[u] = make_float4(0.f, 0.f, 0.f, 0.f);
    double zsum = 0.0;

    const int row0 = blockIdx.x * 64 + wid * 8;
    for (int r = 0; r < 8; r++) {
        const int row = row0 + r;
        const float4* __restrict__ vp =
            reinterpret_cast<const float4*>(adj + (size_t)row * F_IN);
        float4 v[8];
        #pragma unroll
        for (int u = 0; u < 8; u++) v[u] = vp[u * 32 + lane];

        // plain fp32 dot, 4 independent fmaf chains
        float dx = 0.f, dy = 0.f, dz = 0.f, dw = 0.f;
        #pragma unroll
        for (int u = 0; u < 8; u++) {
            dx = __fmaf_rn(v[u].x, wreg[u].x, dx);
            dy = __fmaf_rn(v[u].y, wreg[u].y, dy);
            dz = __fmaf_rn(v[u].z, wreg[u].z, dz);
            dw = __fmaf_rn(v[u].w, wreg[u].w, dw);
        }
        float d = warp_sum_f(__fadd_rn(__fadd_rn(dx, dy), __fadd_rn(dz, dw)));

        float e;
        if (lane == 0) {
            double sc = (double)d + s0;
            sc = sc > 0.0 ? sc : ((double)0.1f) * sc;   // jax fp32 alpha
            g_score32[row] = (float)sc;
            e = expf((float)(sc - Cs));
            zsum += (double)e;
        }
        e = __shfl_sync(0xffffffffu, e, 0);

        #pragma unroll
        for (int u = 0; u < 8; u++) {
            vacc[u].x = __fmaf_rn(e, v[u].x, vacc[u].x);
            vacc[u].y = __fmaf_rn(e, v[u].y, vacc[u].y);
            vacc[u].z = __fmaf_rn(e, v[u].z, vacc[u].z);
            vacc[u].w = __fmaf_rn(e, v[u].w, vacc[u].w);
        }
    }

    if (lane == 0) sh_z[wid] = zsum;

    #pragma unroll
    for (int u = 0; u < 8; u++) {
        const int base = (u * 32 + lane) * 4;
        atomicAdd(&sh_v[base + 0], vacc[u].x);
        atomicAdd(&sh_v[base + 1], vacc[u].y);
        atomicAdd(&sh_v[base + 2], vacc[u].z);
        atomicAdd(&sh_v[base + 3], vacc[u].w);
    }
    __syncthreads();

    if (tid == 0) {
        double z = 0.0;
        #pragma unroll
        for (int w = 0; w < 8; w++) z += sh_z[w];
        atomicAdd(&g_acc.Z, z);
    }
    const float4 sv = reinterpret_cast<const float4*>(sh_v)[tid];
    atomicAdd(&g_acc.v[tid * 4 + 0], sv.x);
    atomicAdd(&g_acc.v[tid * 4 + 1], sv.y);
    atomicAdd(&g_acc.v[tid * 4 + 2], sv.z);
    atomicAdd(&g_acc.v[tid * 4 + 3], sv.w);
}

// ---------------- K3 (merged): att2 + inline fixup | out GEMV ----------
// grid = 128 blocks x 512 thr.
//   blocks 0..63  : attention2 for 512 rows each (+ band fixup in-block)
//   blocks 64..127: out[k] partial over 16 j-values each
__global__ void __launch_bounds__(512) k_post(const float* __restrict__ adj,
                                              const float* __restrict__ W1,
                                              float* __restrict__ att2,
                                              float* __restrict__ out,
                                              int write_att2, int want_out) {
    const int b   = blockIdx.x;
    const int tid = threadIdx.x;

    if (b < 64) {
        if (!write_att2) return;
        __shared__ int sh_n;
        __shared__ int sh_rows[64];
        if (tid == 0) sh_n = 0;
        __syncthreads();

        const double s0 = g_acc.s0;
        const double Cs = shift_Cs(s0, g_acc.sumpos);
        const double eN = g_acc.Z * (1.0 / (double)N_ROWS);   // att>1/N <=> e>Z/N
        const float  eNf   = (float)eN;
        const float  bandf = BANDR * eNf;

        const int row = b * 512 + tid;
        const float s = g_score32[row];
        const float e = expf((float)((double)s - Cs));
        att2[row] = (e > eNf) ? 1.0f : 0.0f;
        if (fabsf(e - eNf) < bandf) {
            int k = atomicAdd(&sh_n, 1);
            if (k < 64) sh_rows[k] = row;
        }
        __syncthreads();

        int n = sh_n; if (n > 64) n = 64;
        const int wid  = tid >> 5;
        const int lane = tid & 31;
        for (int k = wid; k < n; k += 16) {           // warp per flagged row
            const int r = sh_rows[k];
            const float4* __restrict__ vp =
                reinterpret_cast<const float4*>(adj + (size_t)r * F_IN);
            float2 acc = make_float2(0.f, 0.f);
            #pragma unroll
            for (int u = 0; u < 8; u++) {
                const float4 v  = vp[u * 32 + lane];
                const float4 wh = reinterpret_cast<const float4*>(g_w2hi)[u * 32 + lane];
                const float4 wl = reinterpret_cast<const float4*>(g_w2lo)[u * 32 + lane];
                acc = ts_addprod(acc, v.x, wh.x, wl.x);
                acc = ts_addprod(acc, v.y, wh.y, wl.y);
                acc = ts_addprod(acc, v.z, wh.z, wl.z);
                acc = ts_addprod(acc, v.w, wh.w, wl.w);
            }
            double d = (double)acc.x + (double)acc.y;
            #pragma unroll
            for (int off = 16; off > 0; off >>= 1)
                d += __shfl_down_sync(0xffffffffu, d, off);
            if (lane == 0) {
                double sc = d + s0;
                sc = sc > 0.0 ? sc : ((double)0.1f) * sc;
                att2[r] = (exp(sc - Cs) > eN) ? 1.0f : 0.0f;   // double, no log
            }
        }
    } else {
        if (!want_out) return;
        __shared__ float sh_invZ;
        if (tid == 0) sh_invZ = (float)(1.0 / g_acc.Z);
        __syncthreads();
        const int k  = tid;                 // 0..511
        const int j0 = (b - 64) * 16;
        float acc = 0.f;
        #pragma unroll
        for (int j = 0; j < 16; j++)
            acc = __fmaf_rn(g_acc.v[j0 + j], W1[(size_t)(j0 + j) * F_OUT + k], acc);
        atomicAdd(&out[k], acc * sh_invZ);  // out zeroed by memset node
    }
}

// ---------------- launch ----------------
extern "C" void kernel_launch(void* const* d_in, const int* in_sizes, int n_in,
                              void* d_out, int out_size) {
    const float* h   = (const float*)d_in[0];
    const float* adj = (const float*)d_in[1];
    const float* W   = (const float*)d_in[2];
    const float* a   = (const float*)d_in[3];
    const float* W1  = (const float*)d_in[4];
    float* out = (float*)d_out;

    // Output layout (confirmed passing R5..R12):
    //   >= 33280 : [out(512) | attention2(32768)]
    //   == 512   : out only
    //   == 32768 : attention2 only
    bool  want_out = true;
    float* att2    = nullptr;
    if (out_size >= F_OUT + N_ROWS) {
        att2 = out + F_OUT;
    } else if (out_size == N_ROWS) {
        att2 = out;
        want_out = false;
    }

    // Zero accumulators via memset nodes (replaces k_init kernel).
    void* acc_ptr = nullptr;
    cudaGetSymbolAddress(&acc_ptr, g_acc);
    cudaMemsetAsync(acc_ptr, 0, sizeof(Acc), 0);
    if (want_out) cudaMemsetAsync(out, 0, F_OUT * sizeof(float), 0);

    k_w12<<<F_IN / 8, 256>>>(W, a, h);
    k_fused<<<N_ROWS / 64, 256>>>(adj);
    k_post<<<128, 512>>>(adj, W1,
                         att2 ? att2 : out, out,
                         att2 != nullptr ? 1 : 0, want_out ? 1 : 0);
}

// round 15
// speedup vs baseline: 2.2360x; 1.0093x over previous
#include <cuda_runtime.h>

#define N_ROWS 32768
#define F_IN   1024
#define F_OUT  512
#define BANDR  2e-4f

// ---------------- device scratch (no allocations allowed) ----------------
// Packed so ONE cudaMemsetAsync graph node zeroes all per-call accumulators.
struct Acc {
    float  v[F_IN];        // sum_i e_i * adj[i]
    double s0;             // h . (W @ a1)
    double sumpos;         // sum_j max(0, W@a2)
    double Z;              // sum_i exp(s_i - Cs)
};
__device__ Acc   g_acc;
__device__ float g_w2hi[F_IN];
__device__ float g_w2lo[F_IN];
__device__ float g_score32[N_ROWS];

// ---------------- helpers ----------------
__device__ __forceinline__ float warp_sum_f(float x) {
    #pragma unroll
    for (int off = 16; off > 0; off >>= 1)
        x += __shfl_down_sync(0xffffffffu, x, off);
    return x;
}
__device__ __forceinline__ float2 ts_merge(float2 A, float2 B) {
    float s  = __fadd_rn(A.x, B.x);
    float bv = __fsub_rn(s, A.x);
    float av = __fsub_rn(s, bv);
    float e  = __fadd_rn(__fsub_rn(A.x, av), __fsub_rn(B.x, bv));
    return make_float2(s, __fadd_rn(__fadd_rn(A.y, B.y), e));
}
__device__ __forceinline__ float2 ts_addprod(float2 acc, float v, float whi, float wlo) {
    float p  = __fmul_rn(v, whi);
    float pe = __fmaf_rn(v, whi, -p);
    pe = __fmaf_rn(v, wlo, pe);
    return ts_merge(acc, make_float2(p, pe));
}
// single-product version (wlo = 0)
__device__ __forceinline__ float2 ts_addprod1(float2 acc, float v, float w) {
    float p  = __fmul_rn(v, w);
    float pe = __fmaf_rn(v, w, -p);
    return ts_merge(acc, make_float2(p, pe));
}
__device__ __forceinline__ float2 warp_ts_reduce(float2 acc) {
    #pragma unroll
    for (int off = 16; off > 0; off >>= 1) {
        float2 o;
        o.x = __shfl_down_sync(0xffffffffu, acc.x, off);
        o.y = __shfl_down_sync(0xffffffffu, acc.y, off);
        acc = ts_merge(acc, o);
    }
    return acc;
}
// Cs = leaky(C), C = s0 + sum_pos(w2): exact upper bound of scores (adj in [0,1))
__device__ __forceinline__ double shift_Cs(double s0, double sumpos) {
    double C = s0 + sumpos;
    return C > 0.0 ? C : ((double)0.1f) * C;
}

// ---------------- K1: w2 hi/lo, s0, sumpos (block-reduced atomics) ------
// 128 blocks x 256 thr (8 warps); warp-per-row, dual compensated chains.
__global__ void __launch_bounds__(256) k_w12(const float* __restrict__ W,
                                             const float* __restrict__ a,
                                             const float* __restrict__ h) {
    const int wid  = threadIdx.x >> 5;
    const int lane = threadIdx.x & 31;
    const int j    = blockIdx.x * 8 + wid;             // 0..F_IN-1
    const float4* __restrict__ rw = reinterpret_cast<const float4*>(W + (size_t)j * F_OUT);
    const float4* __restrict__ a1 = reinterpret_cast<const float4*>(a);
    const float4* __restrict__ a2 = reinterpret_cast<const float4*>(a + F_OUT);

    // two independent compensated chains per dot (halve serial latency)
    float2 c1a = make_float2(0.f, 0.f), c1b = make_float2(0.f, 0.f);
    float2 c2a = make_float2(0.f, 0.f), c2b = make_float2(0.f, 0.f);
    #pragma unroll
    for (int u = 0; u < 4; u++) {
        const float4 w4 = rw[u * 32 + lane];
        const float4 b1 = __ldg(a1 + u * 32 + lane);
        const float4 b2 = __ldg(a2 + u * 32 + lane);
        c1a = ts_addprod1(c1a, w4.x, b1.x);
        c1b = ts_addprod1(c1b, w4.y, b1.y);
        c1a = ts_addprod1(c1a, w4.z, b1.z);
        c1b = ts_addprod1(c1b, w4.w, b1.w);
        c2a = ts_addprod1(c2a, w4.x, b2.x);
        c2b = ts_addprod1(c2b, w4.y, b2.y);
        c2a = ts_addprod1(c2a, w4.z, b2.z);
        c2b = ts_addprod1(c2b, w4.w, b2.w);
    }
    float2 acc1 = warp_ts_reduce(ts_merge(c1a, c1b));
    float2 acc2 = warp_ts_reduce(ts_merge(c2a, c2b));

    __shared__ double sh_s0[8], sh_sp[8];
    if (lane == 0) {
        double w1 = (double)acc1.x + (double)acc1.y;
        double w2 = (double)acc2.x + (double)acc2.y;
        float hi = (float)w2;
        g_w2hi[j] = hi;
        g_w2lo[j] = (float)(w2 - (double)hi);
        sh_s0[wid] = w1 * (double)h[j];
        sh_sp[wid] = w2 > 0.0 ? w2 : 0.0;
    }
    __syncthreads();
    if (threadIdx.x == 0) {
        double s0 = 0.0, sp = 0.0;
        #pragma unroll
        for (int w = 0; w < 8; w++) { s0 += sh_s0[w]; sp += sh_sp[w]; }
        atomicAdd(&g_acc.s0, s0);          // 128 atomics total (was 1024)
        atomicAdd(&g_acc.sumpos, sp);
    }
}

// ---------------- K2 (fused): scores + e + v + Z, ONE adj pass ----------
// 512 blocks x 256 thr (8 warps); warp handles 8 rows; w2hi in REGISTERS.
__global__ void __launch_bounds__(256) k_fused(const float* __restrict__ adj) {
    __shared__ float  sh_v[F_IN];
    __shared__ double sh_z[8];
    const int tid  = threadIdx.x;
    const int wid  = tid >> 5;
    const int lane = tid & 31;

    sh_v[tid]       = 0.0f;
    sh_v[tid + 256] = 0.0f;
    sh_v[tid + 512] = 0.0f;
    sh_v[tid + 768] = 0.0f;

    // w2hi lane-slice resident in registers for the whole kernel
    float4 wreg[8];
    #pragma unroll
    for (int u = 0; u < 8; u++)
        wreg[u] = reinterpret_cast<const float4*>(g_w2hi)[u * 32 + lane];

    __syncthreads();

    const double s0 = g_acc.s0;
    const double Cs = shift_Cs(s0, g_acc.sumpos);

    float4 vacc[8];
    #pragma unroll
    for (int u = 0; u < 8; u++) vacc[u] = make_float4(0.f, 0.f, 0.f, 0.f);
    double zsum = 0.0;

    const int row0 = blockIdx.x * 64 + wid * 8;
    for (int r = 0; r < 8; r++) {
        const int row = row0 + r;
        const float4* __restrict__ vp =
            reinterpret_cast<const float4*>(adj + (size_t)row * F_IN);
        float4 v[8];
        #pragma unroll
        for (int u = 0; u < 8; u++) v[u] = vp[u * 32 + lane];

        // plain fp32 dot, 4 independent fmaf chains
        float dx = 0.f, dy = 0.f, dz = 0.f, dw = 0.f;
        #pragma unroll
        for (int u = 0; u < 8; u++) {
            dx = __fmaf_rn(v[u].x, wreg[u].x, dx);
            dy = __fmaf_rn(v[u].y, wreg[u].y, dy);
            dz = __fmaf_rn(v[u].z, wreg[u].z, dz);
            dw = __fmaf_rn(v[u].w, wreg[u].w, dw);
        }
        float d = warp_sum_f(__fadd_rn(__fadd_rn(dx, dy), __fadd_rn(dz, dw)));

        float e;
        if (lane == 0) {
            double sc = (double)d + s0;
            sc = sc > 0.0 ? sc : ((double)0.1f) * sc;   // jax fp32 alpha
            g_score32[row] = (float)sc;
            e = expf((float)(sc - Cs));
            zsum += (double)e;
        }
        e = __shfl_sync(0xffffffffu, e, 0);

        #pragma unroll
        for (int u = 0; u < 8; u++) {
            vacc[u].x = __fmaf_rn(e, v[u].x, vacc[u].x);
            vacc[u].y = __fmaf_rn(e, v[u].y, vacc[u].y);
            vacc[u].z = __fmaf_rn(e, v[u].z, vacc[u].z);
            vacc[u].w = __fmaf_rn(e, v[u].w, vacc[u].w);
        }
    }

    if (lane == 0) sh_z[wid] = zsum;

    #pragma unroll
    for (int u = 0; u < 8; u++) {
        const int base = (u * 32 + lane) * 4;
        atomicAdd(&sh_v[base + 0], vacc[u].x);
        atomicAdd(&sh_v[base + 1], vacc[u].y);
        atomicAdd(&sh_v[base + 2], vacc[u].z);
        atomicAdd(&sh_v[base + 3], vacc[u].w);
    }
    __syncthreads();

    if (tid == 0) {
        double z = 0.0;
        #pragma unroll
        for (int w = 0; w < 8; w++) z += sh_z[w];
        atomicAdd(&g_acc.Z, z);
    }
    const float4 sv = reinterpret_cast<const float4*>(sh_v)[tid];
    atomicAdd(&g_acc.v[tid * 4 + 0], sv.x);
    atomicAdd(&g_acc.v[tid * 4 + 1], sv.y);
    atomicAdd(&g_acc.v[tid * 4 + 2], sv.z);
    atomicAdd(&g_acc.v[tid * 4 + 3], sv.w);
}

// ---------------- K3 (merged): att2 + inline fixup | out GEMV ----------
// grid = 128 blocks x 512 thr.
//   blocks 0..63  : attention2 for 512 rows each (+ band fixup in-block)
//   blocks 64..127: out[k] partial over 16 j-values each
__global__ void __launch_bounds__(512) k_post(const float* __restrict__ adj,
                                              const float* __restrict__ W1,
                                              float* __restrict__ att2,
                                              float* __restrict__ out,
                                              int write_att2, int want_out) {
    const int b   = blockIdx.x;
    const int tid = threadIdx.x;

    if (b < 64) {
        if (!write_att2) return;
        __shared__ int sh_n;
        __shared__ int sh_rows[64];
        if (tid == 0) sh_n = 0;
        __syncthreads();

        const double s0 = g_acc.s0;
        const double Cs = shift_Cs(s0, g_acc.sumpos);
        const double eN = g_acc.Z * (1.0 / (double)N_ROWS);   // att>1/N <=> e>Z/N
        const float  eNf   = (float)eN;
        const float  bandf = BANDR * eNf;

        const int row = b * 512 + tid;
        const float s = g_score32[row];
        const float e = expf((float)((double)s - Cs));
        att2[row] = (e > eNf) ? 1.0f : 0.0f;
        if (fabsf(e - eNf) < bandf) {
            int k = atomicAdd(&sh_n, 1);
            if (k < 64) sh_rows[k] = row;
        }
        __syncthreads();

        int n = sh_n; if (n > 64) n = 64;
        const int wid  = tid >> 5;
        const int lane = tid & 31;
        for (int k = wid; k < n; k += 16) {           // warp per flagged row
            const int r = sh_rows[k];
            const float4* __restrict__ vp =
                reinterpret_cast<const float4*>(adj + (size_t)r * F_IN);
            float2 acc = make_float2(0.f, 0.f);
            #pragma unroll
            for (int u = 0; u < 8; u++) {
                const float4 v  = vp[u * 32 + lane];
                const float4 wh = reinterpret_cast<const float4*>(g_w2hi)[u * 32 + lane];
                const float4 wl = reinterpret_cast<const float4*>(g_w2lo)[u * 32 + lane];
                acc = ts_addprod(acc, v.x, wh.x, wl.x);
                acc = ts_addprod(acc, v.y, wh.y, wl.y);
                acc = ts_addprod(acc, v.z, wh.z, wl.z);
                acc = ts_addprod(acc, v.w, wh.w, wl.w);
            }
            double d = (double)acc.x + (double)acc.y;
            #pragma unroll
            for (int off = 16; off > 0; off >>= 1)
                d += __shfl_down_sync(0xffffffffu, d, off);
            if (lane == 0) {
                double sc = d + s0;
                sc = sc > 0.0 ? sc : ((double)0.1f) * sc;
                att2[r] = (exp(sc - Cs) > eN) ? 1.0f : 0.0f;   // double, no log
            }
        }
    } else {
        if (!want_out) return;
        __shared__ float sh_invZ;
        if (tid == 0) sh_invZ = (float)(1.0 / g_acc.Z);
        __syncthreads();
        const int k  = tid;                 // 0..511
        const int j0 = (b - 64) * 16;
        float acc = 0.f;
        #pragma unroll
        for (int j = 0; j < 16; j++)
            acc = __fmaf_rn(g_acc.v[j0 + j], W1[(size_t)(j0 + j) * F_OUT + k], acc);
        atomicAdd(&out[k], acc * sh_invZ);  // out zeroed by memset node
    }
}

// ---------------- launch ----------------
extern "C" void kernel_launch(void* const* d_in, const int* in_sizes, int n_in,
                              void* d_out, int out_size) {
    const float* h   = (const float*)d_in[0];
    const float* adj = (const float*)d_in[1];
    const float* W   = (const float*)d_in[2];
    const float* a   = (const float*)d_in[3];
    const float* W1  = (const float*)d_in[4];
    float* out = (float*)d_out;

    // Output layout (confirmed passing R5..R14):
    //   >= 33280 : [out(512) | attention2(32768)]
    //   == 512   : out only
    //   == 32768 : attention2 only
    bool  want_out = true;
    float* att2    = nullptr;
    if (out_size >= F_OUT + N_ROWS) {
        att2 = out + F_OUT;
    } else if (out_size == N_ROWS) {
        att2 = out;
        want_out = false;
    }

    // Zero accumulators via memset nodes (replaces k_init kernel).
    void* acc_ptr = nullptr;
    cudaGetSymbolAddress(&acc_ptr, g_acc);
    cudaMemsetAsync(acc_ptr, 0, sizeof(Acc), 0);
    if (want_out) cudaMemsetAsync(out, 0, F_OUT * sizeof(float), 0);

    k_w12<<<F_IN / 8, 256>>>(W, a, h);
    k_fused<<<N_ROWS / 64, 256>>>(adj);
    k_post<<<128, 512>>>(adj, W1,
                         att2 ? att2 : out, out,
                         att2 != nullptr ? 1 : 0, want_out ? 1 : 0);
}